// round 2
// baseline (speedup 1.0000x reference)
#include <cuda_runtime.h>
#include <stdint.h>

#define THREADS 128
#define ROWS    128      // rows per block
#define PCOUNT  64       // predicates
#define PAD     129      // conflict-free row stride in shared
#define C_MAX   128
#define EROWS   128      // E-table entries: exp(+g_p) at p, exp(-g_p) at p+64

__device__ uint4  g_pk[C_MAX];   // packed pre-multiplied indices
__device__ float4 g_swl[C_MAX];  // sign*clamped_weight per literal

__device__ __forceinline__ float frcp(float x){ float y; asm("rcp.approx.f32 %0, %1;" : "=f"(y) : "f"(x)); return y; }
__device__ __forceinline__ float fex2(float x){ float y; asm("ex2.approx.f32 %0, %1;" : "=f"(y) : "f"(x)); return y; }

// Build the clause table once per launch: indices premultiplied by PAD, sign
// folded into e-index (p for +, p+64 for -) and into the weight (+w / -w).
// literal_idx may physically be int32 (JAX x64-disabled downcasts jnp.int64)
// or int64 — detect at runtime. Int64 interpretation of int32 data fuses two
// random indices (high word nonzero w.p. 63/64 per entry), so requiring all
// of the first 192 int64 views to lie in [0,64) discriminates reliably while
// staying inside the smaller buffer's bounds.
__global__ void prep_kernel(const float* __restrict__ cw,
                            const void* __restrict__ litraw,
                            const int* __restrict__ sgn, int C)
{
    __shared__ int sh_is64;
    if (threadIdx.x == 0){
        const long long* v64 = (const long long*)litraw;
        int n = (C * 3) / 2;        // stay within int32-buffer bounds
        int ok = 1;
        for (int k = 0; k < n; k++){
            long long v = v64[k];
            if (v < 0 || v >= PCOUNT){ ok = 0; break; }
        }
        sh_is64 = ok;
    }
    __syncthreads();
    const int is64 = sh_is64;

    int c = blockIdx.x * blockDim.x + threadIdx.x;
    if (c >= C) return;
    float w = fminf(fmaxf(cw[c], 0.0f), 500.0f);   // clamp(MIN_WEIGHT, MAX_WEIGHT)
    unsigned e[3], a[3]; float s[3];
    #pragma unroll
    for (int l = 0; l < 3; l++){
        int p = is64 ? (int)((const long long*)litraw)[c*3 + l]
                     :       ((const int*)litraw)[c*3 + l];
        int sb = sgn[c*3 + l];        // 0 or 1; sign = 2*sb - 1
        e[l] = (unsigned)((p + (sb ? 0 : PCOUNT)) * PAD);  // sb=1 -> exp(+g), sb=0 -> exp(-g)
        a[l] = (unsigned)(p * PAD);
        s[l] = sb ? w : -w;
    }
    g_pk[c]  = make_uint4(e[0] | (e[1] << 16), e[2] | (a[0] << 16), a[1] | (a[2] << 16), 0u);
    g_swl[c] = make_float4(s[0], s[1], s[2], 0.0f);
}

__global__ void __launch_bounds__(THREADS)
main_kernel(const float* __restrict__ ga, float* __restrict__ out, int C, int B)
{
    extern __shared__ float sh[];
    // Distinct restrict regions: lets ptxas prefetch E-gathers of later clauses
    // past acc stores of earlier ones. Acc RMWs stay ordered among themselves
    // (same pointer) -> correct for duplicate predicates within/across clauses.
    float* __restrict__ E = sh;                        // EROWS * PAD floats
    float* __restrict__ A = sh + EROWS*PAD;            // PCOUNT * PAD floats
    uint4*  CI = (uint4*)(sh + EROWS*PAD + PCOUNT*PAD);
    float4* CW = (float4*)(CI + C_MAX);

    const int tid = threadIdx.x;
    const long long rowbase = (long long)blockIdx.x * ROWS;
    long long rem = (long long)B - rowbase;
    const int nrows = rem < ROWS ? (int)rem : ROWS;
    const size_t base = (size_t)rowbase * PCOUNT;

    if (tid < C){ CI[tid] = g_pk[tid]; CW[tid] = g_swl[tid]; }

    #pragma unroll
    for (int p = 0; p < PCOUNT; p++) A[p*PAD + tid] = 0.0f;

    // Phase A: coalesced load of the 128x64 tile; build E-table.
    // Only 128 distinct exponentials exist per row: exp(+g) and rcp of it.
    const float4* ga4 = (const float4*)(ga + base);
    const float L2E = 1.4426950408889634f;
    for (int i = tid; i < ROWS*PCOUNT/4; i += THREADS){
        int o = i * 4, row = o >> 6, p = o & (PCOUNT-1);
        if (row < nrows){
            float4 g = ga4[i];
            float t;
            t = fex2(g.x*L2E); E[(p  )*PAD+row] = t; E[(p+PCOUNT  )*PAD+row] = frcp(t);
            t = fex2(g.y*L2E); E[(p+1)*PAD+row] = t; E[(p+PCOUNT+1)*PAD+row] = frcp(t);
            t = fex2(g.z*L2E); E[(p+2)*PAD+row] = t; E[(p+PCOUNT+2)*PAD+row] = frcp(t);
            t = fex2(g.w*L2E); E[(p+3)*PAD+row] = t; E[(p+PCOUNT+3)*PAD+row] = frcp(t);
        }
    }
    __syncthreads();

    // Phase B: clause loop. Thread owns row `tid`. All gathers/RMWs are
    // conflict-free (lane stride = PAD floats); const loads are broadcasts.
    #pragma unroll 8
    for (int c = 0; c < C; c++){
        uint4 ci = CI[c]; float4 cw = CW[c];
        int e0 = (int)(ci.x & 0xFFFF), e1 = (int)(ci.x >> 16);
        int e2 = (int)(ci.y & 0xFFFF), a0 = (int)(ci.y >> 16);
        int a1 = (int)(ci.z & 0xFFFF), a2 = (int)(ci.z >> 16);
        float x0 = E[e0 + tid], x1 = E[e1 + tid], x2 = E[e2 + tid];
        float r  = frcp(x0 + x1 + x2);                 // 1/sum(exp)
        A[a0 + tid] = fmaf(cw.x, x0*r, A[a0 + tid]);   // sign*w*softmax scatter
        A[a1 + tid] = fmaf(cw.y, x1*r, A[a1 + tid]);
        A[a2 + tid] = fmaf(cw.z, x2*r, A[a2 + tid]);
    }
    __syncthreads();

    // Phase C: coalesced store of the 128x64 output tile.
    float4* out4 = (float4*)(out + base);
    for (int i = tid; i < ROWS*PCOUNT/4; i += THREADS){
        int o = i*4, row = o >> 6, p = o & (PCOUNT-1);
        if (row < nrows){
            float4 v;
            v.x = A[(p  )*PAD + row];
            v.y = A[(p+1)*PAD + row];
            v.z = A[(p+2)*PAD + row];
            v.w = A[(p+3)*PAD + row];
            out4[i] = v;
        }
    }
}

extern "C" void kernel_launch(void* const* d_in, const int* in_sizes, int n_in,
                              void* d_out, int out_size)
{
    const float* ga  = (const float*)d_in[0];      // ground_atoms [B,64] f32
    const float* cw  = (const float*)d_in[1];      // clause_weights [C] f32
    const void*  lit = d_in[2];                    // literal_idx [C,3] i32 or i64
    const int*   sgn = (const int*)d_in[3];        // sign_bits [C,3] i32
    float* out = (float*)d_out;

    int C = in_sizes[1];
    int B = in_sizes[0] / PCOUNT;
    int nblocks = (B + ROWS - 1) / ROWS;
    size_t smem = (size_t)(EROWS*PAD + PCOUNT*PAD) * sizeof(float)
                + C_MAX * (sizeof(uint4) + sizeof(float4));   // ~100.8 KB

    cudaFuncSetAttribute(main_kernel, cudaFuncAttributeMaxDynamicSharedMemorySize, (int)smem);
    prep_kernel<<<1, THREADS>>>(cw, lit, sgn, C);
    main_kernel<<<nblocks, THREADS, smem>>>(ga, out, C, B);
}